// round 1
// baseline (speedup 1.0000x reference)
#include <cuda_runtime.h>
#include <math.h>

#define DIM 256
#define INV_SQRT2 0.70710678118654752f
#define SILU_SCALE 1.6666666666666667f

#define MAX_E 200000

// Scratch (allocation-free per harness rules)
__device__ float g_x[(size_t)MAX_E * DIM];
__device__ float g_h[(size_t)MAX_E * DIM];

__device__ __forceinline__ float scaled_silu(float v) {
    return v * SILU_SCALE / (1.0f + __expf(-v));
}

// ---------------------------------------------------------------------------
// Tiled fp32 GEMM: C[M,256] = epilogue(A[M,K] @ B[K,256])
//   EPI=0 : C = scaled_silu(AB)
//   EPI=1 : C = (Res + scaled_silu(AB)) * INV_SQRT2
// BM=128, BN=128, BK=16, 256 threads, 8x8 per thread.
// ---------------------------------------------------------------------------
template <int EPI>
__global__ void __launch_bounds__(256) gemm_epi_kernel(
    const float* __restrict__ A, const float* __restrict__ B,
    float* __restrict__ C, const float* __restrict__ Res,
    int M, int K)
{
    __shared__ float As[16][132];   // [k][m], pitch 132 (16B-aligned rows)
    __shared__ float Bs[16][132];   // [k][n]

    const int tid = threadIdx.x;
    const int block_row = blockIdx.x * 128;
    const int block_col = blockIdx.y * 128;

    const int tm = (tid >> 4) << 3;   // 0..120 step 8
    const int tn = (tid & 15) << 3;   // 0..120 step 8

    float acc[8][8];
    #pragma unroll
    for (int i = 0; i < 8; i++)
        #pragma unroll
        for (int j = 0; j < 8; j++)
            acc[i][j] = 0.0f;

    for (int k0 = 0; k0 < K; k0 += 16) {
        // ---- load A tile (128x16) transposed into As[k][m] ----
        #pragma unroll
        for (int it = 0; it < 2; it++) {
            int f  = tid + it * 256;      // 0..511
            int r  = f >> 2;              // 0..127 (m within tile)
            int c4 = (f & 3) << 2;        // 0,4,8,12 (k within tile)
            int grow = block_row + r;
            float4 v = make_float4(0.f, 0.f, 0.f, 0.f);
            if (grow < M)
                v = *reinterpret_cast<const float4*>(A + (size_t)grow * K + k0 + c4);
            As[c4 + 0][r] = v.x;
            As[c4 + 1][r] = v.y;
            As[c4 + 2][r] = v.z;
            As[c4 + 3][r] = v.w;
        }
        // ---- load B tile (16x128) into Bs[k][n] ----
        #pragma unroll
        for (int it = 0; it < 2; it++) {
            int f  = tid + it * 256;      // 0..511
            int r  = f >> 5;              // 0..15  (k within tile)
            int c4 = (f & 31) << 2;       // 0..124 (n within tile)
            float4 v = *reinterpret_cast<const float4*>(
                B + (size_t)(k0 + r) * DIM + block_col + c4);
            *reinterpret_cast<float4*>(&Bs[r][c4]) = v;
        }
        __syncthreads();

        // ---- compute ----
        #pragma unroll
        for (int k = 0; k < 16; k++) {
            float4 a0 = *reinterpret_cast<const float4*>(&As[k][tm]);
            float4 a1 = *reinterpret_cast<const float4*>(&As[k][tm + 4]);
            float4 b0 = *reinterpret_cast<const float4*>(&Bs[k][tn]);
            float4 b1 = *reinterpret_cast<const float4*>(&Bs[k][tn + 4]);
            float a[8] = {a0.x, a0.y, a0.z, a0.w, a1.x, a1.y, a1.z, a1.w};
            float b[8] = {b0.x, b0.y, b0.z, b0.w, b1.x, b1.y, b1.z, b1.w};
            #pragma unroll
            for (int i = 0; i < 8; i++)
                #pragma unroll
                for (int j = 0; j < 8; j++)
                    acc[i][j] = fmaf(a[i], b[j], acc[i][j]);
        }
        __syncthreads();
    }

    // ---- epilogue ----
    #pragma unroll
    for (int i = 0; i < 8; i++) {
        int row = block_row + tm + i;
        if (row >= M) break;
        size_t base = (size_t)row * DIM + block_col + tn;
        float out[8];
        if (EPI == 0) {
            #pragma unroll
            for (int j = 0; j < 8; j++) out[j] = scaled_silu(acc[i][j]);
        } else {
            float4 r0 = *reinterpret_cast<const float4*>(Res + base);
            float4 r1 = *reinterpret_cast<const float4*>(Res + base + 4);
            float rr[8] = {r0.x, r0.y, r0.z, r0.w, r1.x, r1.y, r1.z, r1.w};
            #pragma unroll
            for (int j = 0; j < 8; j++)
                out[j] = (rr[j] + scaled_silu(acc[i][j])) * INV_SQRT2;
        }
        *reinterpret_cast<float4*>(C + base)     = make_float4(out[0], out[1], out[2], out[3]);
        *reinterpret_cast<float4*>(C + base + 4) = make_float4(out[4], out[5], out[6], out[7]);
    }
}

// ---------------------------------------------------------------------------
// Zero the output buffer
// ---------------------------------------------------------------------------
__global__ void zero_kernel(float* __restrict__ out, int n) {
    int i = blockIdx.x * blockDim.x + threadIdx.x;
    if (i < n) out[i] = 0.0f;
}

// ---------------------------------------------------------------------------
// Final projection + scatter: warp per edge.
//   F = dot(x[e,:], W_out); atomicAdd(out[idx[e],c], F * edge_vec[e,c])
// ---------------------------------------------------------------------------
__global__ void __launch_bounds__(256) force_scatter_kernel(
    const float* __restrict__ x, const float* __restrict__ Wout,
    const float* __restrict__ edge_vec, const int* __restrict__ edge_idx,
    float* __restrict__ out, int E)
{
    int gwarp = (blockIdx.x * blockDim.x + threadIdx.x) >> 5;
    int lane = threadIdx.x & 31;
    if (gwarp >= E) return;

    const float* xr = x + (size_t)gwarp * DIM;
    float s = 0.0f;
    #pragma unroll
    for (int i = 0; i < 8; i++)
        s = fmaf(xr[lane + i * 32], Wout[lane + i * 32], s);
    #pragma unroll
    for (int o = 16; o > 0; o >>= 1)
        s += __shfl_xor_sync(0xFFFFFFFFu, s, o);
    // all lanes have the sum after butterfly
    if (lane < 3) {
        float fv = s * edge_vec[(size_t)gwarp * 3 + lane];
        atomicAdd(&out[(size_t)edge_idx[gwarp] * 3 + lane], fv);
    }
}

extern "C" void kernel_launch(void* const* d_in, const int* in_sizes, int n_in,
                              void* d_out, int out_size)
{
    const float* x_cat    = (const float*)d_in[0];
    const float* edge_vec = (const float*)d_in[1];
    const int*   edge_idx = (const int*)  d_in[2];
    const float* W_in     = (const float*)d_in[3];
    const float* W_r1a    = (const float*)d_in[4];
    const float* W_r1b    = (const float*)d_in[5];
    const float* W_r2a    = (const float*)d_in[6];
    const float* W_r2b    = (const float*)d_in[7];
    const float* W_out    = (const float*)d_in[8];

    int E  = in_sizes[1] / 3;          // 200000
    int K1 = in_sizes[0] / E;          // 1280

    float *xb, *hb;
    cudaGetSymbolAddress((void**)&xb, g_x);
    cudaGetSymbolAddress((void**)&hb, g_h);

    float* out = (float*)d_out;

    // zero output (poisoned by harness)
    zero_kernel<<<(out_size + 255) / 256, 256>>>(out, out_size);

    dim3 grid((E + 127) / 128, DIM / 128);
    dim3 blk(256);

    // x = scaled_silu(x_cat @ W_in)
    gemm_epi_kernel<0><<<grid, blk>>>(x_cat, W_in, xb, nullptr, E, K1);
    // h = scaled_silu(x @ W_r1a)
    gemm_epi_kernel<0><<<grid, blk>>>(xb, W_r1a, hb, nullptr, E, DIM);
    // x = (x + scaled_silu(h @ W_r1b)) * INV_SQRT2   (in-place safe: same-elem read/write per thread)
    gemm_epi_kernel<1><<<grid, blk>>>(hb, W_r1b, xb, xb, E, DIM);
    // h = scaled_silu(x @ W_r2a)
    gemm_epi_kernel<0><<<grid, blk>>>(xb, W_r2a, hb, nullptr, E, DIM);
    // x = (x + scaled_silu(h @ W_r2b)) * INV_SQRT2
    gemm_epi_kernel<1><<<grid, blk>>>(hb, W_r2b, xb, xb, E, DIM);

    // F = x @ W_out; scatter F * edge_vec into atoms
    int warps_per_blk = 256 / 32;
    force_scatter_kernel<<<(E + warps_per_blk - 1) / warps_per_blk, 256>>>(
        xb, W_out, edge_vec, edge_idx, out, E);
}

// round 7
// speedup vs baseline: 1.6608x; 1.6608x over previous
#include <cuda_runtime.h>
#include <cuda_bf16.h>
#include <cstdint>

#define EMAX 200000
#define DIM 256
#define INV_SQRT2 0.70710678118654752f
#define SILU_SCALE 1.6666666666666667f

// ---------------- scratch (device globals; no runtime alloc) ----------------
__device__ unsigned short g_ahi[(size_t)EMAX * 1280];
__device__ unsigned short g_alo[(size_t)EMAX * 1280];
__device__ unsigned short g_bhi[(size_t)EMAX * DIM];
__device__ unsigned short g_blo[(size_t)EMAX * DIM];
__device__ float          g_res[(size_t)EMAX * DIM];
#define W_TOTAL (1280 * 256 + 4 * 256 * 256)
__device__ unsigned short g_whi[W_TOTAL];
__device__ unsigned short g_wlo[W_TOTAL];

// ---------------- PTX helpers (sm_80+ baseline: valid at target sm_103) -----
__device__ __forceinline__ uint32_t smem_u32(const void* p) {
    uint32_t a;
    asm("{ .reg .u64 t; cvta.to.shared.u64 t, %1; cvt.u32.u64 %0, t; }" : "=r"(a) : "l"(p));
    return a;
}
__device__ __forceinline__ void cp16(uint32_t dst, const void* src, int sz) {
    asm volatile("cp.async.ca.shared.global [%0], [%1], 16, %2;"
                 :: "r"(dst), "l"(src), "r"(sz) : "memory");
}
__device__ __forceinline__ void ldsm_x4(uint32_t* r, uint32_t addr) {
    asm volatile("ldmatrix.sync.aligned.m8n8.x4.shared.b16 {%0,%1,%2,%3}, [%4];"
                 : "=r"(r[0]), "=r"(r[1]), "=r"(r[2]), "=r"(r[3]) : "r"(addr));
}
__device__ __forceinline__ void ldsm_x2(uint32_t* r, uint32_t addr) {
    asm volatile("ldmatrix.sync.aligned.m8n8.x2.shared.b16 {%0,%1}, [%2];"
                 : "=r"(r[0]), "=r"(r[1]) : "r"(addr));
}
__device__ __forceinline__ void mma16816(float* c, const uint32_t* a, const uint32_t* b) {
    asm volatile(
        "mma.sync.aligned.m16n8k16.row.col.f32.bf16.bf16.f32 "
        "{%0,%1,%2,%3}, {%4,%5,%6,%7}, {%8,%9}, {%0,%1,%2,%3};"
        : "+f"(c[0]), "+f"(c[1]), "+f"(c[2]), "+f"(c[3])
        : "r"(a[0]), "r"(a[1]), "r"(a[2]), "r"(a[3]), "r"(b[0]), "r"(b[1]));
}

__device__ __forceinline__ float scaled_silu(float v) {
    return v * SILU_SCALE / (1.0f + __expf(-v));
}

// SMEM stage layout (bytes): tiles 128 rows x 32 bf16, row pitch 80B (conflict-free ldmatrix)
#define PITCH    80
#define OFF_ALO  10240
#define OFF_BHI  20480
#define OFF_BLO  30720
#define STAGE    40960
#define SMEM_BYTES (2 * STAGE)

// ---------------------------------------------------------------------------
// HMMA GEMM: C[M,256] = epi(A[M,K] @ B[256,K]^T), bf16 hi/lo split (3 MMAs).
// Block tile 128x128 (grid.y=2 for N=256), 8 warps, warp tile 32x64.
// MODE 0: OutF = silu;  OutHi/Lo = split(silu)
// MODE 1: OutHi/Lo = split(silu)
// MODE 2: v=(Res+silu)*c; OutF=v; OutHi/Lo=split(v)
// MODE 3: v=(Res+silu)*c; partial dot(v,Wout) over this N-block; atomic scatter
// ---------------------------------------------------------------------------
template <int MODE>
__global__ void __launch_bounds__(256, 1) hmma_gemm(
    const unsigned short* __restrict__ Ahi, const unsigned short* __restrict__ Alo,
    const unsigned short* __restrict__ Bhi, const unsigned short* __restrict__ Blo,
    float* __restrict__ OutF, unsigned short* __restrict__ OutHi, unsigned short* __restrict__ OutLo,
    const float* __restrict__ Res,
    const float* __restrict__ Wout, const float* __restrict__ EdgeVec,
    const int* __restrict__ EdgeIdx, float* __restrict__ AtomOut,
    int M, int K)
{
    extern __shared__ char sm[];
    const uint32_t sb = smem_u32(sm);
    const int tid = threadIdx.x;
    const int l = tid & 31;
    const int w = tid >> 5;
    const int block_row = blockIdx.x * 128;
    const int bn = blockIdx.y * 128;
    const int wm = (w & 3) * 32;     // warp row offset in tile
    const int wn = (w >> 2) * 64;    // warp col offset in tile
    const int NC = K >> 5;

    float acc[2][8][4];
    #pragma unroll
    for (int i = 0; i < 2; ++i)
        #pragma unroll
        for (int j = 0; j < 8; ++j)
            #pragma unroll
            for (int q = 0; q < 4; ++q) acc[i][j][q] = 0.0f;

    auto load_chunk = [&](int c, int s) {
        const int k0 = c << 5;
        const uint32_t st = sb + s * STAGE;
        #pragma unroll
        for (int it = 0; it < 2; ++it) {
            int f = tid + (it << 8);          // 0..511
            int r = f >> 2, q = f & 3;        // row 0..127, 16B-quad 0..3
            int gr = block_row + r;
            int vz = (gr < M) ? 16 : 0;
            size_t aoff = (size_t)(gr < M ? gr : 0) * K + k0 + q * 8;
            uint32_t so = r * PITCH + q * 16;
            cp16(st + so,           Ahi + aoff, vz);
            cp16(st + OFF_ALO + so, Alo + aoff, vz);
            size_t boff = (size_t)(bn + r) * K + k0 + q * 8;
            cp16(st + OFF_BHI + so, Bhi + boff, 16);
            cp16(st + OFF_BLO + so, Blo + boff, 16);
        }
    };

    auto compute = [&](int s) {
        const uint32_t st = sb + s * STAGE;
        #pragma unroll
        for (int kk = 0; kk < 32; kk += 16) {
            uint32_t ah[2][4], al[2][4];
            #pragma unroll
            for (int mi = 0; mi < 2; ++mi) {
                uint32_t ad = st + (wm + mi * 16 + (l & 15)) * PITCH + (kk + (l >> 4) * 8) * 2;
                ldsm_x4(ah[mi], ad);
                ldsm_x4(al[mi], ad + OFF_ALO);
            }
            #pragma unroll
            for (int ni = 0; ni < 8; ++ni) {
                uint32_t bd = st + OFF_BHI + (wn + ni * 8 + (l & 7)) * PITCH
                            + (kk + ((l >> 3) & 1) * 8) * 2;
                uint32_t bh[2], bl[2];
                ldsm_x2(bh, bd);
                ldsm_x2(bl, bd + (OFF_BLO - OFF_BHI));
                #pragma unroll
                for (int mi = 0; mi < 2; ++mi) {
                    mma16816(acc[mi][ni], ah[mi], bh);
                    mma16816(acc[mi][ni], ah[mi], bl);
                    mma16816(acc[mi][ni], al[mi], bh);
                }
            }
        }
    };

    load_chunk(0, 0);
    asm volatile("cp.async.commit_group;" ::: "memory");
    for (int c = 0; c < NC; ++c) {
        if (c + 1 < NC) {
            load_chunk(c + 1, (c + 1) & 1);
            asm volatile("cp.async.commit_group;" ::: "memory");
            asm volatile("cp.async.wait_group 1;" ::: "memory");
        } else {
            asm volatile("cp.async.wait_group 0;" ::: "memory");
        }
        __syncthreads();
        compute(c & 1);
        __syncthreads();
    }

    // ---------------- epilogue ----------------
    const int tq = l >> 2, tr = l & 3;
    #pragma unroll
    for (int mi = 0; mi < 2; ++mi) {
        #pragma unroll
        for (int half = 0; half < 2; ++half) {
            const int row = block_row + wm + mi * 16 + tq + half * 8;
            const bool ok = row < M;
            float dot = 0.0f;
            #pragma unroll
            for (int ni = 0; ni < 8; ++ni) {
                const int n = bn + wn + ni * 8 + tr * 2;
                float v0 = scaled_silu(acc[mi][ni][half * 2 + 0]);
                float v1 = scaled_silu(acc[mi][ni][half * 2 + 1]);
                if (MODE >= 2) {
                    float2 rr = ok ? *reinterpret_cast<const float2*>(Res + (size_t)row * 256 + n)
                                   : make_float2(0.0f, 0.0f);
                    v0 = (rr.x + v0) * INV_SQRT2;
                    v1 = (rr.y + v1) * INV_SQRT2;
                }
                if (MODE == 3) {
                    dot += v0 * __ldg(Wout + n) + v1 * __ldg(Wout + n + 1);
                } else if (ok) {
                    size_t base = (size_t)row * 256 + n;
                    if (MODE == 0 || MODE == 2)
                        *reinterpret_cast<float2*>(OutF + base) = make_float2(v0, v1);
                    __nv_bfloat16 h0 = __float2bfloat16(v0);
                    __nv_bfloat16 h1 = __float2bfloat16(v1);
                    __nv_bfloat162 hh; hh.x = h0; hh.y = h1;
                    __nv_bfloat162 ll;
                    ll.x = __float2bfloat16(v0 - __bfloat162float(h0));
                    ll.y = __float2bfloat16(v1 - __bfloat162float(h1));
                    *reinterpret_cast<uint32_t*>(OutHi + base) = *reinterpret_cast<uint32_t*>(&hh);
                    *reinterpret_cast<uint32_t*>(OutLo + base) = *reinterpret_cast<uint32_t*>(&ll);
                }
            }
            if (MODE == 3) {
                dot += __shfl_xor_sync(0xFFFFFFFFu, dot, 1);
                dot += __shfl_xor_sync(0xFFFFFFFFu, dot, 2);
                if (ok && tr == 0) {
                    int a = EdgeIdx[row];
                    #pragma unroll
                    for (int cc = 0; cc < 3; ++cc) {
                        float fv = dot * __ldg(EdgeVec + (size_t)row * 3 + cc);
                        atomicAdd(&AtomOut[(size_t)a * 3 + cc], fv);
                    }
                }
            }
        }
    }
}

// ---------------------------------------------------------------------------
// elementwise fp32 -> bf16 hi/lo split (n multiple of 4)
// ---------------------------------------------------------------------------
__global__ void conv_split(const float* __restrict__ x, unsigned short* __restrict__ hi,
                           unsigned short* __restrict__ lo, size_t n)
{
    size_t i = ((size_t)blockIdx.x * blockDim.x + threadIdx.x) * 4;
    if (i >= n) return;
    float4 v = *reinterpret_cast<const float4*>(x + i);
    float a[4] = {v.x, v.y, v.z, v.w};
    uint32_t ph[2], pl[2];
    #pragma unroll
    for (int q = 0; q < 2; ++q) {
        __nv_bfloat16 h0 = __float2bfloat16(a[2 * q]);
        __nv_bfloat16 h1 = __float2bfloat16(a[2 * q + 1]);
        __nv_bfloat162 hh; hh.x = h0; hh.y = h1;
        __nv_bfloat162 ll;
        ll.x = __float2bfloat16(a[2 * q] - __bfloat162float(h0));
        ll.y = __float2bfloat16(a[2 * q + 1] - __bfloat162float(h1));
        ph[q] = *reinterpret_cast<uint32_t*>(&hh);
        pl[q] = *reinterpret_cast<uint32_t*>(&ll);
    }
    *reinterpret_cast<uint2*>(hi + i) = make_uint2(ph[0], ph[1]);
    *reinterpret_cast<uint2*>(lo + i) = make_uint2(pl[0], pl[1]);
}

// ---------------------------------------------------------------------------
// weight transpose + split: W[K,256] fp32 -> B[256,K] bf16 hi/lo
// ---------------------------------------------------------------------------
__global__ void conv_w(const float* __restrict__ W, unsigned short* __restrict__ bhi,
                       unsigned short* __restrict__ blo, int K)
{
    int idx = blockIdx.x * blockDim.x + threadIdx.x;
    if (idx >= K * 256) return;
    int k = idx >> 8, n = idx & 255;
    float v = W[idx];
    __nv_bfloat16 h = __float2bfloat16(v);
    __nv_bfloat16 l = __float2bfloat16(v - __bfloat162float(h));
    bhi[(size_t)n * K + k] = *reinterpret_cast<unsigned short*>(&h);
    blo[(size_t)n * K + k] = *reinterpret_cast<unsigned short*>(&l);
}

__global__ void zero_kernel(float* __restrict__ out, int n) {
    int i = blockIdx.x * blockDim.x + threadIdx.x;
    if (i < n) out[i] = 0.0f;
}

// ---------------------------------------------------------------------------
extern "C" void kernel_launch(void* const* d_in, const int* in_sizes, int n_in,
                              void* d_out, int out_size)
{
    const float* x_cat    = (const float*)d_in[0];
    const float* edge_vec = (const float*)d_in[1];
    const int*   edge_idx = (const int*)  d_in[2];
    const float* W_in     = (const float*)d_in[3];
    const float* W_r1a    = (const float*)d_in[4];
    const float* W_r1b    = (const float*)d_in[5];
    const float* W_r2a    = (const float*)d_in[6];
    const float* W_r2b    = (const float*)d_in[7];
    const float* W_out    = (const float*)d_in[8];

    int E  = in_sizes[1] / 3;        // 200000
    int K1 = in_sizes[0] / E;        // 1280

    unsigned short *ahi, *alo, *bhi, *blo, *whi, *wlo;
    float* res;
    cudaGetSymbolAddress((void**)&ahi, g_ahi);
    cudaGetSymbolAddress((void**)&alo, g_alo);
    cudaGetSymbolAddress((void**)&bhi, g_bhi);
    cudaGetSymbolAddress((void**)&blo, g_blo);
    cudaGetSymbolAddress((void**)&whi, g_whi);
    cudaGetSymbolAddress((void**)&wlo, g_wlo);
    cudaGetSymbolAddress((void**)&res, g_res);

    float* out = (float*)d_out;

    cudaFuncSetAttribute(hmma_gemm<0>, cudaFuncAttributeMaxDynamicSharedMemorySize, SMEM_BYTES);
    cudaFuncSetAttribute(hmma_gemm<1>, cudaFuncAttributeMaxDynamicSharedMemorySize, SMEM_BYTES);
    cudaFuncSetAttribute(hmma_gemm<2>, cudaFuncAttributeMaxDynamicSharedMemorySize, SMEM_BYTES);
    cudaFuncSetAttribute(hmma_gemm<3>, cudaFuncAttributeMaxDynamicSharedMemorySize, SMEM_BYTES);

    zero_kernel<<<(out_size + 255) / 256, 256>>>(out, out_size);

    // weight offsets in packed [N,K] buffers
    size_t off_in  = 0;
    size_t off_r1a = (size_t)1280 * 256;
    size_t off_r1b = off_r1a + 65536;
    size_t off_r2a = off_r1b + 65536;
    size_t off_r2b = off_r2a + 65536;
    conv_w<<<(K1 * 256 + 255) / 256, 256>>>(W_in,  whi + off_in,  wlo + off_in,  K1);
    conv_w<<<(65536 + 255) / 256, 256>>>(W_r1a, whi + off_r1a, wlo + off_r1a, 256);
    conv_w<<<(65536 + 255) / 256, 256>>>(W_r1b, whi + off_r1b, wlo + off_r1b, 256);
    conv_w<<<(65536 + 255) / 256, 256>>>(W_r2a, whi + off_r2a, wlo + off_r2a, 256);
    conv_w<<<(65536 + 255) / 256, 256>>>(W_r2b, whi + off_r2b, wlo + off_r2b, 256);

    // x_cat -> hi/lo
    size_t nconv = (size_t)E * K1;
    conv_split<<<(unsigned)((nconv / 4 + 255) / 256), 256>>>(x_cat, ahi, alo, nconv);

    dim3 grid((E + 127) / 128, 2);
    dim3 blk(256);

    // GEMM1: silu(x_cat @ W_in) -> res(fp32) + bhi/blo
    hmma_gemm<0><<<grid, blk, SMEM_BYTES>>>(ahi, alo, whi + off_in, wlo + off_in,
                                            res, bhi, blo, nullptr,
                                            nullptr, nullptr, nullptr, nullptr, E, K1);
    // GEMM2: silu(x @ W_r1a) -> ahi/alo
    hmma_gemm<1><<<grid, blk, SMEM_BYTES>>>(bhi, blo, whi + off_r1a, wlo + off_r1a,
                                            nullptr, ahi, alo, nullptr,
                                            nullptr, nullptr, nullptr, nullptr, E, 256);
    // GEMM3: x = (res + silu(h @ W_r1b)) * c -> res(fp32) + bhi/blo
    hmma_gemm<2><<<grid, blk, SMEM_BYTES>>>(ahi, alo, whi + off_r1b, wlo + off_r1b,
                                            res, bhi, blo, res,
                                            nullptr, nullptr, nullptr, nullptr, E, 256);
    // GEMM4: silu(x @ W_r2a) -> ahi/alo
    hmma_gemm<1><<<grid, blk, SMEM_BYTES>>>(bhi, blo, whi + off_r2a, wlo + off_r2a,
                                            nullptr, ahi, alo, nullptr,
                                            nullptr, nullptr, nullptr, nullptr, E, 256);
    // GEMM5: x = (res + silu(h @ W_r2b)) * c; F = x@Wout; scatter F*edge_vec
    hmma_gemm<3><<<grid, blk, SMEM_BYTES>>>(ahi, alo, whi + off_r2b, wlo + off_r2b,
                                            nullptr, nullptr, nullptr, res,
                                            W_out, edge_vec, edge_idx, out, E, 256);
}